// round 8
// baseline (speedup 1.0000x reference)
#include <cuda_runtime.h>
#include <cuda_fp16.h>
#include <math.h>

#define HID   32
#define BATCH 2
#define NMAX  55296
#define EMAX  221184
#define COLT  256

typedef unsigned long long ull;

__device__ __forceinline__ void fma2(ull& acc, ull a, ull b) {
    asm("fma.rn.f32x2 %0, %1, %2, %0;" : "+l"(acc) : "l"(a), "l"(b));
}
__device__ __forceinline__ ull pack2(float lo, float hi) {
    ull r; asm("mov.b64 %0, {%1, %2};" : "=l"(r) : "f"(lo), "f"(hi)); return r;
}
__device__ __forceinline__ float2 unpack2(ull v) {
    float2 r; asm("mov.b64 {%0, %1}, %2;" : "=f"(r.x), "=f"(r.y) : "l"(v)); return r;
}

// ---- scratch (device globals: allocation-free rule) ----
__device__ float  g_t[EMAX * HID];                         //  28 MB
// layout: [e][y][o][hl]  (y = h>>3, hl = h&7): half index = e*1024 + y*256 + o*8 + hl
__device__ __half g_We[(size_t)EMAX * HID * HID];          // 453 MB fp16
__device__ float  g_state[BATCH * NMAX * HID];             //  14 MB
__device__ float  g_agg[BATCH * NMAX * HID];               //  14 MB
__device__ float2 g_gruW[3 * HID * HID];                   // 24 KB packed (wih,whh) transposed

// ---------------- h0 = ReLU(x@pw1+pb1)@pw2+pb2  (+ agg init fused) ----------------
__global__ void node_mlp_kernel(const float* __restrict__ x,
                                const float* __restrict__ pw1, const float* __restrict__ pb1,
                                const float* __restrict__ pw2, const float* __restrict__ pb2,
                                const float* __restrict__ conv_b, int rows) {
    __shared__ float w1[HID * HID], w2[HID * HID], b1[HID], b2[HID], cb[HID];
    int tid = threadIdx.x;
    for (int i = tid; i < HID * HID; i += blockDim.x) { w1[i] = pw1[i]; w2[i] = pw2[i]; }
    if (tid < HID) { b1[tid] = pb1[tid]; b2[tid] = pb2[tid]; cb[tid] = conv_b[tid]; }
    __syncthreads();
    int warp = tid >> 5, lane = tid & 31;
    int row = blockIdx.x * (blockDim.x >> 5) + warp;
    if (row >= rows) return;
    float xv = x[row * HID + lane];
    float h1 = b1[lane];
#pragma unroll
    for (int k = 0; k < HID; k++)
        h1 = fmaf(__shfl_sync(0xffffffffu, xv, k), w1[k * HID + lane], h1);
    h1 = fmaxf(h1, 0.f);
    float h2 = b2[lane];
#pragma unroll
    for (int k = 0; k < HID; k++)
        h2 = fmaf(__shfl_sync(0xffffffffu, h1, k), w2[k * HID + lane], h2);
    g_state[row * HID + lane] = h2;
    g_agg[row * HID + lane] = cb[lane];     // fused init_agg
}

// ---------------- t = ReLU(er@ew1+eb1)  [E,32]  (+ GRU weight pack in block 0) ----------------
__global__ void edge_t_kernel(const float* __restrict__ er,
                              const float* __restrict__ ew1,
                              const float* __restrict__ eb1,
                              const float* __restrict__ wih,
                              const float* __restrict__ whh, int E) {
    int idx = blockIdx.x * blockDim.x + threadIdx.x;
    if (blockIdx.x == 0) {
        for (int i = threadIdx.x; i < 3 * HID * HID; i += blockDim.x) {
            int g = i >> 10, r = i & 1023, k = r >> 5, l = r & 31;
            int j = g * HID + l;
            g_gruW[i] = make_float2(wih[j * HID + k], whh[j * HID + k]);
        }
    }
    if (idx >= E * HID) return;
    int e = idx >> 5, l = idx & 31;
    float acc = eb1[l];
#pragma unroll
    for (int m = 0; m < 4; m++)
        acc = fmaf(er[e * 4 + m], ew1[m * HID + l], acc);
    g_t[idx] = fmaxf(acc, 0.f);
}

// ---------------- We = t @ ew2 + eb2, fp16, blocked layout [e][y][o][8h] ----------------
// smem-broadcast doubled t: inner loop per k = 4 LDS.64(w) + 8 LDS.64(t bcast) + 32 FMA2
__global__ void __launch_bounds__(256, 2)
we_gemm_kernel(const float* __restrict__ ew2, const float* __restrict__ eb2, int E) {
    __shared__ float2 ws2[HID][4][32];      // 32 KB weights
    __shared__ float2 t2s[8][8][HID];       // 16 KB doubled t: [warp][j][k]
    __shared__ float bs[COLT];
    int col0 = blockIdx.y * COLT;
    int tid = threadIdx.x;
    for (int i = tid; i < HID * 128; i += blockDim.x) {
        int k = i >> 7, r = i & 127, q = r >> 5, l = r & 31;
        ws2[k][q][l] = make_float2(ew2[k * (HID * HID) + col0 + q * 64 + l],
                                   ew2[k * (HID * HID) + col0 + q * 64 + 32 + l]);
    }
    for (int i = tid; i < COLT; i += blockDim.x) bs[i] = eb2[col0 + i];
    __syncthreads();

    int warp = tid >> 5, lane = tid & 31;
    int nwarps = blockDim.x >> 5;
    int groups = (E + 7) >> 3;
    float bias[8];
#pragma unroll
    for (int m = 0; m < 8; m++) bias[m] = bs[m * 32 + lane];

    for (int g = blockIdx.x * nwarps + warp; g < groups; g += gridDim.x * nwarps) {
        int e0 = g * 8;
        // stage doubled t for this warp's 8 edges: lane writes k=lane entry
#pragma unroll
        for (int j = 0; j < 8; j++) {
            float tv = (e0 + j < E) ? g_t[(e0 + j) * HID + lane] : 0.f;
            t2s[warp][j][lane] = make_float2(tv, tv);
        }
        __syncwarp();

        ull acc[8][4];
#pragma unroll
        for (int j = 0; j < 8; j++)
#pragma unroll
            for (int q = 0; q < 4; q++) acc[j][q] = 0ull;

#pragma unroll
        for (int k = 0; k < HID; k++) {
            ull w0 = *(const ull*)&ws2[k][0][lane];
            ull w1 = *(const ull*)&ws2[k][1][lane];
            ull w2 = *(const ull*)&ws2[k][2][lane];
            ull w3 = *(const ull*)&ws2[k][3][lane];
#pragma unroll
            for (int j = 0; j < 8; j++) {
                ull p = *(const ull*)&t2s[warp][j][k];   // uniform-address broadcast
                fma2(acc[j][0], p, w0);
                fma2(acc[j][1], p, w1);
                fma2(acc[j][2], p, w2);
                fma2(acc[j][3], p, w3);
            }
        }
#pragma unroll
        for (int j = 0; j < 8; j++) {
            int e = e0 + j;
            if (e < E) {
                float2 v0 = unpack2(acc[j][0]);
                float2 v1 = unpack2(acc[j][1]);
                float2 v2 = unpack2(acc[j][2]);
                float2 v3 = unpack2(acc[j][3]);
                __half2 p0 = __floats2half2_rn(v0.x + bias[0], v0.y + bias[1]);
                __half2 p1 = __floats2half2_rn(v1.x + bias[2], v1.y + bias[3]);
                __half2 p2 = __floats2half2_rn(v2.x + bias[4], v2.y + bias[5]);
                __half2 p3 = __floats2half2_rn(v3.x + bias[6], v3.y + bias[7]);
                uint4 val;
                val.x = *(unsigned*)&p0;
                val.y = *(unsigned*)&p1;
                val.z = *(unsigned*)&p2;
                val.w = *(unsigned*)&p3;
                *(uint4*)(g_We + (size_t)e * (HID * HID) + blockIdx.y * 256 + lane * 8) = val;
            }
        }
        __syncwarp();
    }
}

// ---------------- msg + scatter: warp per 2 edges (MLP x2), fp16 We, v4 red ----------------
__global__ void msg_kernel(const int* __restrict__ src, const int* __restrict__ dst,
                           int E, int N) {
    int pair = (blockIdx.x * blockDim.x + threadIdx.x) >> 5;
    int lane = threadIdx.x & 31;
    int e0 = pair * 2;
    if (e0 >= E) return;
    int e1 = e0 + 1;
    bool has1 = (e1 < E);
    int sA = src[e0], dA = dst[e0];
    int sB = has1 ? src[e1] : sA;
    int dB = has1 ? dst[e1] : dA;

    float sa0 = g_state[sA * HID + lane];
    float sb0 = g_state[N * HID + sA * HID + lane];
    float sa1 = g_state[sB * HID + lane];
    float sb1 = g_state[N * HID + sB * HID + lane];

    const __half* WA = g_We + (size_t)e0 * (HID * HID) + lane * 8;
    const __half* WB = g_We + (size_t)e1 * (HID * HID) + lane * 8;
    uint4 wvA[4], wvB[4];
#pragma unroll
    for (int q = 0; q < 4; q++) {
        wvA[q] = *(const uint4*)(WA + q * 256);
        wvB[q] = has1 ? *(const uint4*)(WB + q * 256) : make_uint4(0, 0, 0, 0);
    }

    float mA0 = 0.f, mA1 = 0.f, mB0 = 0.f, mB1 = 0.f;
#pragma unroll
    for (int q = 0; q < 4; q++) {
        const __half2* hpA = (const __half2*)&wvA[q];
        const __half2* hpB = (const __half2*)&wvB[q];
#pragma unroll
        for (int j = 0; j < 4; j++) {
            float2 wA = __half22float2(hpA[j]);
            float2 wB = __half22float2(hpB[j]);
            int h = q * 8 + j * 2;
            float aA0 = __shfl_sync(0xffffffffu, sa0, h);
            float bA0 = __shfl_sync(0xffffffffu, sb0, h);
            float aA1 = __shfl_sync(0xffffffffu, sa0, h + 1);
            float bA1 = __shfl_sync(0xffffffffu, sb0, h + 1);
            float aB0 = __shfl_sync(0xffffffffu, sa1, h);
            float bB0 = __shfl_sync(0xffffffffu, sb1, h);
            float aB1 = __shfl_sync(0xffffffffu, sa1, h + 1);
            float bB1 = __shfl_sync(0xffffffffu, sb1, h + 1);
            mA0 = fmaf(aA0, wA.x, mA0); mA1 = fmaf(bA0, wA.x, mA1);
            mA0 = fmaf(aA1, wA.y, mA0); mA1 = fmaf(bA1, wA.y, mA1);
            mB0 = fmaf(aB0, wB.x, mB0); mB1 = fmaf(bB0, wB.x, mB1);
            mB0 = fmaf(aB1, wB.y, mB0); mB1 = fmaf(bB1, wB.y, mB1);
        }
    }
    int q4 = (lane & 7) * 4;
    {
        float t0 = __shfl_sync(0xffffffffu, mA0, q4 + 0);
        float t1 = __shfl_sync(0xffffffffu, mA0, q4 + 1);
        float t2 = __shfl_sync(0xffffffffu, mA0, q4 + 2);
        float t3 = __shfl_sync(0xffffffffu, mA0, q4 + 3);
        float u0 = __shfl_sync(0xffffffffu, mA1, q4 + 0);
        float u1 = __shfl_sync(0xffffffffu, mA1, q4 + 1);
        float u2 = __shfl_sync(0xffffffffu, mA1, q4 + 2);
        float u3 = __shfl_sync(0xffffffffu, mA1, q4 + 3);
        if (lane < 16) {
            float v0, v1, v2, v3; float* p;
            if (lane < 8) { v0 = t0; v1 = t1; v2 = t2; v3 = t3; p = &g_agg[dA * HID + q4]; }
            else          { v0 = u0; v1 = u1; v2 = u2; v3 = u3; p = &g_agg[N * HID + dA * HID + q4]; }
            asm volatile("red.global.add.v4.f32 [%0], {%1, %2, %3, %4};"
                         :: "l"(p), "f"(v0), "f"(v1), "f"(v2), "f"(v3) : "memory");
        }
    }
    if (has1) {
        float t0 = __shfl_sync(0xffffffffu, mB0, q4 + 0);
        float t1 = __shfl_sync(0xffffffffu, mB0, q4 + 1);
        float t2 = __shfl_sync(0xffffffffu, mB0, q4 + 2);
        float t3 = __shfl_sync(0xffffffffu, mB0, q4 + 3);
        float u0 = __shfl_sync(0xffffffffu, mB1, q4 + 0);
        float u1 = __shfl_sync(0xffffffffu, mB1, q4 + 1);
        float u2 = __shfl_sync(0xffffffffu, mB1, q4 + 2);
        float u3 = __shfl_sync(0xffffffffu, mB1, q4 + 3);
        if (lane < 16) {
            float v0, v1, v2, v3; float* p;
            if (lane < 8) { v0 = t0; v1 = t1; v2 = t2; v3 = t3; p = &g_agg[dB * HID + q4]; }
            else          { v0 = u0; v1 = u1; v2 = u2; v3 = u3; p = &g_agg[N * HID + dB * HID + q4]; }
            asm volatile("red.global.add.v4.f32 [%0], {%1, %2, %3, %4};"
                         :: "l"(p), "f"(v0), "f"(v1), "f"(v2), "f"(v3) : "memory");
        }
    }
}

// ---------------- GRU: quasi-persistent, warp = node (grid-stride), f32x2 packed ----------------
__global__ void gru_kernel(const float* __restrict__ bih, const float* __restrict__ bhh,
                           const float* __restrict__ conv_b,
                           float* __restrict__ dout, int N, int final_step) {
    __shared__ float2 W2[3 * HID * HID];   // 24 KB, layout [(g*32+k)*32+l]
    __shared__ float bi[3 * HID], bh[3 * HID], cb[HID];
    int tid = threadIdx.x;
    for (int i = tid; i < 3 * HID * HID; i += blockDim.x) W2[i] = g_gruW[i];
    for (int i = tid; i < 3 * HID; i += blockDim.x) { bi[i] = bih[i]; bh[i] = bhh[i]; }
    if (tid < HID) cb[tid] = conv_b[tid];
    __syncthreads();

    int warp = tid >> 5, lane = tid & 31;
    int nwarps = blockDim.x >> 5;
    for (int n = blockIdx.x * nwarps + warp; n < N; n += gridDim.x * nwarps) {
        int i0 = n * HID + lane;
        int i1 = N * HID + n * HID + lane;
        float a0 = fmaxf(g_agg[i0], 0.f), a1 = fmaxf(g_agg[i1], 0.f);
        float h0 = g_state[i0],          h1 = g_state[i1];

        ull r0 = pack2(bi[lane], bh[lane]);
        ull z0 = pack2(bi[32 + lane], bh[32 + lane]);
        ull n0 = pack2(bi[64 + lane], bh[64 + lane]);
        ull r1 = r0, z1 = z0, n1 = n0;
#pragma unroll
        for (int k = 0; k < HID; k++) {
            float ak0 = __shfl_sync(0xffffffffu, a0, k);
            float hk0 = __shfl_sync(0xffffffffu, h0, k);
            float ak1 = __shfl_sync(0xffffffffu, a1, k);
            float hk1 = __shfl_sync(0xffffffffu, h1, k);
            ull xh0 = pack2(ak0, hk0);
            ull xh1 = pack2(ak1, hk1);
            ull wr = *(const ull*)&W2[(0 * HID + k) * HID + lane];
            ull wz = *(const ull*)&W2[(1 * HID + k) * HID + lane];
            ull wn = *(const ull*)&W2[(2 * HID + k) * HID + lane];
            fma2(r0, xh0, wr); fma2(r1, xh1, wr);
            fma2(z0, xh0, wz); fma2(z1, xh1, wz);
            fma2(n0, xh0, wn); fma2(n1, xh1, wn);
        }
        float2 vr0 = unpack2(r0), vz0 = unpack2(z0), vn0 = unpack2(n0);
        float2 vr1 = unpack2(r1), vz1 = unpack2(z1), vn1 = unpack2(n1);

        float rr0 = 1.f / (1.f + expf(-(vr0.x + vr0.y)));
        float zz0 = 1.f / (1.f + expf(-(vz0.x + vz0.y)));
        float nn0 = tanhf(vn0.x + rr0 * vn0.y);
        float out0 = (1.f - zz0) * nn0 + zz0 * h0;

        float rr1 = 1.f / (1.f + expf(-(vr1.x + vr1.y)));
        float zz1 = 1.f / (1.f + expf(-(vz1.x + vz1.y)));
        float nn1 = tanhf(vn1.x + rr1 * vn1.y);
        float out1 = (1.f - zz1) * nn1 + zz1 * h1;

        g_state[i0] = out0;
        g_state[i1] = out1;
        if (final_step) {
            dout[i0] = out0;
            dout[i1] = out1;
        } else {
            g_agg[i0] = cb[lane];
            g_agg[i1] = cb[lane];
        }
    }
}

extern "C" void kernel_launch(void* const* d_in, const int* in_sizes, int n_in,
                              void* d_out, int out_size) {
    const float* x      = (const float*)d_in[0];
    const float* er     = (const float*)d_in[1];
    const float* pw1    = (const float*)d_in[2];
    const float* pb1    = (const float*)d_in[3];
    const float* pw2    = (const float*)d_in[4];
    const float* pb2    = (const float*)d_in[5];
    const float* ew1    = (const float*)d_in[6];
    const float* eb1    = (const float*)d_in[7];
    const float* ew2    = (const float*)d_in[8];
    const float* eb2    = (const float*)d_in[9];
    const float* conv_b = (const float*)d_in[10];
    const float* wih    = (const float*)d_in[11];
    const float* whh    = (const float*)d_in[12];
    const float* bih    = (const float*)d_in[13];
    const float* bhh    = (const float*)d_in[14];
    const int*   esrc   = (const int*)d_in[15];
    const int*   edst   = (const int*)d_in[16];

    int E = in_sizes[15];
    int N = in_sizes[0] / (BATCH * HID);
    int rows = BATCH * N;

    node_mlp_kernel<<<(rows + 7) / 8, 256>>>(x, pw1, pb1, pw2, pb2, conv_b, rows);
    edge_t_kernel<<<(E * HID + 255) / 256, 256>>>(er, ew1, eb1, wih, whh, E);
    {
        dim3 grid(1728, 4);
        we_gemm_kernel<<<grid, 256>>>(ew2, eb2, E);
    }

    for (int step = 0; step < 3; step++) {
        msg_kernel<<<(E / 2 + 7) / 8, 256>>>(esrc, edst, E, N);
        gru_kernel<<<1184, 256>>>(bih, bhh, conv_b, (float*)d_out, N, step == 2);
    }
}

// round 13
// speedup vs baseline: 1.0111x; 1.0111x over previous
#include <cuda_runtime.h>
#include <cuda_fp16.h>
#include <mma.h>
#include <math.h>

using namespace nvcuda;

#define HID   32
#define BATCH 2
#define NMAX  55296
#define EMAX  221184
#define COLT  256

typedef unsigned long long ull;

__device__ __forceinline__ void fma2(ull& acc, ull a, ull b) {
    asm("fma.rn.f32x2 %0, %1, %2, %0;" : "+l"(acc) : "l"(a), "l"(b));
}
__device__ __forceinline__ ull pack2(float lo, float hi) {
    ull r; asm("mov.b64 %0, {%1, %2};" : "=l"(r) : "f"(lo), "f"(hi)); return r;
}
__device__ __forceinline__ float2 unpack2(ull v) {
    float2 r; asm("mov.b64 {%0, %1}, %2;" : "=f"(r.x), "=f"(r.y) : "l"(v)); return r;
}

// ---- scratch (device globals: allocation-free rule) ----
__device__ __half g_th[EMAX * HID];                        //  14 MB fp16 t
__device__ __half g_ew2h[HID * HID * HID];                 //  64 KB fp16 ew2 [k][1024]
// layout: [e][y][o][hl]  (y = h>>3, hl = h&7): half index = e*1024 + y*256 + o*8 + hl
__device__ __half g_We[(size_t)EMAX * HID * HID];          // 453 MB fp16
__device__ float  g_state[BATCH * NMAX * HID];             //  14 MB
__device__ float  g_agg[BATCH * NMAX * HID];               //  14 MB
__device__ float2 g_gruW[3 * HID * HID];                   // 24 KB packed (wih,whh) transposed

// ---------------- h0 = ReLU(x@pw1+pb1)@pw2+pb2  (+ agg init fused) ----------------
__global__ void node_mlp_kernel(const float* __restrict__ x,
                                const float* __restrict__ pw1, const float* __restrict__ pb1,
                                const float* __restrict__ pw2, const float* __restrict__ pb2,
                                const float* __restrict__ conv_b, int rows) {
    __shared__ float w1[HID * HID], w2[HID * HID], b1[HID], b2[HID], cb[HID];
    int tid = threadIdx.x;
    for (int i = tid; i < HID * HID; i += blockDim.x) { w1[i] = pw1[i]; w2[i] = pw2[i]; }
    if (tid < HID) { b1[tid] = pb1[tid]; b2[tid] = pb2[tid]; cb[tid] = conv_b[tid]; }
    __syncthreads();
    int warp = tid >> 5, lane = tid & 31;
    int row = blockIdx.x * (blockDim.x >> 5) + warp;
    if (row >= rows) return;
    float xv = x[row * HID + lane];
    float h1 = b1[lane];
#pragma unroll
    for (int k = 0; k < HID; k++)
        h1 = fmaf(__shfl_sync(0xffffffffu, xv, k), w1[k * HID + lane], h1);
    h1 = fmaxf(h1, 0.f);
    float h2 = b2[lane];
#pragma unroll
    for (int k = 0; k < HID; k++)
        h2 = fmaf(__shfl_sync(0xffffffffu, h1, k), w2[k * HID + lane], h2);
    g_state[row * HID + lane] = h2;
    g_agg[row * HID + lane] = cb[lane];     // fused init_agg
}

// ------- t = ReLU(er@ew1+eb1) -> fp16  (+ GRU weight pack + ew2 fp16 pack, block 0) -------
__global__ void edge_t_kernel(const float* __restrict__ er,
                              const float* __restrict__ ew1,
                              const float* __restrict__ eb1,
                              const float* __restrict__ ew2,
                              const float* __restrict__ wih,
                              const float* __restrict__ whh, int E) {
    int idx = blockIdx.x * blockDim.x + threadIdx.x;
    if (blockIdx.x == 0) {
        for (int i = threadIdx.x; i < 3 * HID * HID; i += blockDim.x) {
            int g = i >> 10, r = i & 1023, k = r >> 5, l = r & 31;
            int j = g * HID + l;
            g_gruW[i] = make_float2(wih[j * HID + k], whh[j * HID + k]);
        }
        for (int i = threadIdx.x; i < HID * HID * HID; i += blockDim.x)
            g_ew2h[i] = __float2half(ew2[i]);
    }
    if (idx >= E * HID) return;
    int e = idx >> 5, l = idx & 31;
    float acc = eb1[l];
#pragma unroll
    for (int m = 0; m < 4; m++)
        acc = fmaf(er[e * 4 + m], ew1[m * HID + l], acc);
    g_th[idx] = __float2half(fmaxf(acc, 0.f));
}

// ---------------- We = t @ ew2 + eb2 via wmma HMMA, blocked fp16 output ----------------
// CTA = 16 edges, 4 warps; warp = y-group (8 h = 256 cols). Each edge's 512B output
// block is assembled in registers and written with dense STG.128 (no repack staging).
__global__ void __launch_bounds__(128)
we_gemm_kernel(const float* __restrict__ eb2, int E) {
    __shared__ float cstage[4][16][36];   // per-warp C tile, padded (conflict-free)
    int warp = threadIdx.x >> 5, lane = threadIdx.x & 31;
    int e0 = blockIdx.x * 16;
    if (e0 >= E) return;
    int y = warp;

    wmma::fragment<wmma::matrix_a, 16, 16, 16, __half, wmma::row_major> a0, a1;
    wmma::load_matrix_sync(a0, g_th + (size_t)e0 * HID, HID);
    wmma::load_matrix_sync(a1, g_th + (size_t)e0 * HID + 16, HID);

    float (*cs)[36] = cstage[warp];
    unsigned outw[16][4];

#pragma unroll
    for (int i = 0; i < 4; i++) {
        float ve[16], vo[16];
#pragma unroll
        for (int par = 0; par < 2; par++) {
            int h = y * 8 + 2 * i + par;
#pragma unroll
            for (int cf = 0; cf < 2; cf++) {
                wmma::fragment<wmma::matrix_b, 16, 16, 16, __half, wmma::row_major> b;
                wmma::fragment<wmma::accumulator, 16, 16, 16, float> c;
                wmma::fill_fragment(c, 0.0f);
                wmma::load_matrix_sync(b, g_ew2h + 0 * 1024 + h * 32 + cf * 16, 1024);
                wmma::mma_sync(c, a0, b, c);
                wmma::load_matrix_sync(b, g_ew2h + 16 * 1024 + h * 32 + cf * 16, 1024);
                wmma::mma_sync(c, a1, b, c);
                wmma::store_matrix_sync(&cs[0][cf * 16], c, 36, wmma::mem_row_major);
            }
            __syncwarp();
            float bias = eb2[h * 32 + lane];
            float* dv = par ? vo : ve;
#pragma unroll
            for (int e = 0; e < 16; e++) dv[e] = cs[e][lane] + bias;
            __syncwarp();
        }
#pragma unroll
        for (int e = 0; e < 16; e++) {
            __half2 hp = __floats2half2_rn(ve[e], vo[e]);
            outw[e][i] = *(unsigned*)&hp;
        }
    }
#pragma unroll
    for (int e = 0; e < 16; e++) {
        uint4 val = make_uint4(outw[e][0], outw[e][1], outw[e][2], outw[e][3]);
        *(uint4*)(g_We + (size_t)(e0 + e) * (HID * HID) + y * 256 + lane * 8) = val;
    }
}

// ---------------- msg + scatter: warp per 2 edges (MLP x2), fp16 We, v4 red ----------------
__global__ void msg_kernel(const int* __restrict__ src, const int* __restrict__ dst,
                           int E, int N) {
    int pair = (blockIdx.x * blockDim.x + threadIdx.x) >> 5;
    int lane = threadIdx.x & 31;
    int e0 = pair * 2;
    if (e0 >= E) return;
    int e1 = e0 + 1;
    bool has1 = (e1 < E);
    int sA = src[e0], dA = dst[e0];
    int sB = has1 ? src[e1] : sA;
    int dB = has1 ? dst[e1] : dA;

    float sa0 = g_state[sA * HID + lane];
    float sb0 = g_state[N * HID + sA * HID + lane];
    float sa1 = g_state[sB * HID + lane];
    float sb1 = g_state[N * HID + sB * HID + lane];

    const __half* WA = g_We + (size_t)e0 * (HID * HID) + lane * 8;
    const __half* WB = g_We + (size_t)e1 * (HID * HID) + lane * 8;
    uint4 wvA[4], wvB[4];
#pragma unroll
    for (int q = 0; q < 4; q++) {
        wvA[q] = *(const uint4*)(WA + q * 256);
        wvB[q] = has1 ? *(const uint4*)(WB + q * 256) : make_uint4(0, 0, 0, 0);
    }

    float mA0 = 0.f, mA1 = 0.f, mB0 = 0.f, mB1 = 0.f;
#pragma unroll
    for (int q = 0; q < 4; q++) {
        const __half2* hpA = (const __half2*)&wvA[q];
        const __half2* hpB = (const __half2*)&wvB[q];
#pragma unroll
        for (int j = 0; j < 4; j++) {
            float2 wA = __half22float2(hpA[j]);
            float2 wB = __half22float2(hpB[j]);
            int h = q * 8 + j * 2;
            float aA0 = __shfl_sync(0xffffffffu, sa0, h);
            float bA0 = __shfl_sync(0xffffffffu, sb0, h);
            float aA1 = __shfl_sync(0xffffffffu, sa0, h + 1);
            float bA1 = __shfl_sync(0xffffffffu, sb0, h + 1);
            float aB0 = __shfl_sync(0xffffffffu, sa1, h);
            float bB0 = __shfl_sync(0xffffffffu, sb1, h);
            float aB1 = __shfl_sync(0xffffffffu, sa1, h + 1);
            float bB1 = __shfl_sync(0xffffffffu, sb1, h + 1);
            mA0 = fmaf(aA0, wA.x, mA0); mA1 = fmaf(bA0, wA.x, mA1);
            mA0 = fmaf(aA1, wA.y, mA0); mA1 = fmaf(bA1, wA.y, mA1);
            mB0 = fmaf(aB0, wB.x, mB0); mB1 = fmaf(bB0, wB.x, mB1);
            mB0 = fmaf(aB1, wB.y, mB0); mB1 = fmaf(bB1, wB.y, mB1);
        }
    }
    int q4 = (lane & 7) * 4;
    {
        float t0 = __shfl_sync(0xffffffffu, mA0, q4 + 0);
        float t1 = __shfl_sync(0xffffffffu, mA0, q4 + 1);
        float t2 = __shfl_sync(0xffffffffu, mA0, q4 + 2);
        float t3 = __shfl_sync(0xffffffffu, mA0, q4 + 3);
        float u0 = __shfl_sync(0xffffffffu, mA1, q4 + 0);
        float u1 = __shfl_sync(0xffffffffu, mA1, q4 + 1);
        float u2 = __shfl_sync(0xffffffffu, mA1, q4 + 2);
        float u3 = __shfl_sync(0xffffffffu, mA1, q4 + 3);
        if (lane < 16) {
            float v0, v1, v2, v3; float* p;
            if (lane < 8) { v0 = t0; v1 = t1; v2 = t2; v3 = t3; p = &g_agg[dA * HID + q4]; }
            else          { v0 = u0; v1 = u1; v2 = u2; v3 = u3; p = &g_agg[N * HID + dA * HID + q4]; }
            asm volatile("red.global.add.v4.f32 [%0], {%1, %2, %3, %4};"
                         :: "l"(p), "f"(v0), "f"(v1), "f"(v2), "f"(v3) : "memory");
        }
    }
    if (has1) {
        float t0 = __shfl_sync(0xffffffffu, mB0, q4 + 0);
        float t1 = __shfl_sync(0xffffffffu, mB0, q4 + 1);
        float t2 = __shfl_sync(0xffffffffu, mB0, q4 + 2);
        float t3 = __shfl_sync(0xffffffffu, mB0, q4 + 3);
        float u0 = __shfl_sync(0xffffffffu, mB1, q4 + 0);
        float u1 = __shfl_sync(0xffffffffu, mB1, q4 + 1);
        float u2 = __shfl_sync(0xffffffffu, mB1, q4 + 2);
        float u3 = __shfl_sync(0xffffffffu, mB1, q4 + 3);
        if (lane < 16) {
            float v0, v1, v2, v3; float* p;
            if (lane < 8) { v0 = t0; v1 = t1; v2 = t2; v3 = t3; p = &g_agg[dB * HID + q4]; }
            else          { v0 = u0; v1 = u1; v2 = u2; v3 = u3; p = &g_agg[N * HID + dB * HID + q4]; }
            asm volatile("red.global.add.v4.f32 [%0], {%1, %2, %3, %4};"
                         :: "l"(p), "f"(v0), "f"(v1), "f"(v2), "f"(v3) : "memory");
        }
    }
}

// ---------------- GRU: quasi-persistent, warp = node (grid-stride), f32x2 packed ----------------
__global__ void gru_kernel(const float* __restrict__ bih, const float* __restrict__ bhh,
                           const float* __restrict__ conv_b,
                           float* __restrict__ dout, int N, int final_step) {
    __shared__ float2 W2[3 * HID * HID];   // 24 KB, layout [(g*32+k)*32+l]
    __shared__ float bi[3 * HID], bh[3 * HID], cb[HID];
    int tid = threadIdx.x;
    for (int i = tid; i < 3 * HID * HID; i += blockDim.x) W2[i] = g_gruW[i];
    for (int i = tid; i < 3 * HID; i += blockDim.x) { bi[i] = bih[i]; bh[i] = bhh[i]; }
    if (tid < HID) cb[tid] = conv_b[tid];
    __syncthreads();

    int warp = tid >> 5, lane = tid & 31;
    int nwarps = blockDim.x >> 5;
    for (int n = blockIdx.x * nwarps + warp; n < N; n += gridDim.x * nwarps) {
        int i0 = n * HID + lane;
        int i1 = N * HID + n * HID + lane;
        float a0 = fmaxf(g_agg[i0], 0.f), a1 = fmaxf(g_agg[i1], 0.f);
        float h0 = g_state[i0],          h1 = g_state[i1];

        ull r0 = pack2(bi[lane], bh[lane]);
        ull z0 = pack2(bi[32 + lane], bh[32 + lane]);
        ull n0 = pack2(bi[64 + lane], bh[64 + lane]);
        ull r1 = r0, z1 = z0, n1 = n0;
#pragma unroll
        for (int k = 0; k < HID; k++) {
            float ak0 = __shfl_sync(0xffffffffu, a0, k);
            float hk0 = __shfl_sync(0xffffffffu, h0, k);
            float ak1 = __shfl_sync(0xffffffffu, a1, k);
            float hk1 = __shfl_sync(0xffffffffu, h1, k);
            ull xh0 = pack2(ak0, hk0);
            ull xh1 = pack2(ak1, hk1);
            ull wr = *(const ull*)&W2[(0 * HID + k) * HID + lane];
            ull wz = *(const ull*)&W2[(1 * HID + k) * HID + lane];
            ull wn = *(const ull*)&W2[(2 * HID + k) * HID + lane];
            fma2(r0, xh0, wr); fma2(r1, xh1, wr);
            fma2(z0, xh0, wz); fma2(z1, xh1, wz);
            fma2(n0, xh0, wn); fma2(n1, xh1, wn);
        }
        float2 vr0 = unpack2(r0), vz0 = unpack2(z0), vn0 = unpack2(n0);
        float2 vr1 = unpack2(r1), vz1 = unpack2(z1), vn1 = unpack2(n1);

        float rr0 = 1.f / (1.f + expf(-(vr0.x + vr0.y)));
        float zz0 = 1.f / (1.f + expf(-(vz0.x + vz0.y)));
        float nn0 = tanhf(vn0.x + rr0 * vn0.y);
        float out0 = (1.f - zz0) * nn0 + zz0 * h0;

        float rr1 = 1.f / (1.f + expf(-(vr1.x + vr1.y)));
        float zz1 = 1.f / (1.f + expf(-(vz1.x + vz1.y)));
        float nn1 = tanhf(vn1.x + rr1 * vn1.y);
        float out1 = (1.f - zz1) * nn1 + zz1 * h1;

        g_state[i0] = out0;
        g_state[i1] = out1;
        if (final_step) {
            dout[i0] = out0;
            dout[i1] = out1;
        } else {
            g_agg[i0] = cb[lane];
            g_agg[i1] = cb[lane];
        }
    }
}

extern "C" void kernel_launch(void* const* d_in, const int* in_sizes, int n_in,
                              void* d_out, int out_size) {
    const float* x      = (const float*)d_in[0];
    const float* er     = (const float*)d_in[1];
    const float* pw1    = (const float*)d_in[2];
    const float* pb1    = (const float*)d_in[3];
    const float* pw2    = (const float*)d_in[4];
    const float* pb2    = (const float*)d_in[5];
    const float* ew1    = (const float*)d_in[6];
    const float* eb1    = (const float*)d_in[7];
    const float* ew2    = (const float*)d_in[8];
    const float* eb2    = (const float*)d_in[9];
    const float* conv_b = (const float*)d_in[10];
    const float* wih    = (const float*)d_in[11];
    const float* whh    = (const float*)d_in[12];
    const float* bih    = (const float*)d_in[13];
    const float* bhh    = (const float*)d_in[14];
    const int*   esrc   = (const int*)d_in[15];
    const int*   edst   = (const int*)d_in[16];

    int E = in_sizes[15];
    int N = in_sizes[0] / (BATCH * HID);
    int rows = BATCH * N;

    node_mlp_kernel<<<(rows + 7) / 8, 256>>>(x, pw1, pb1, pw2, pb2, conv_b, rows);
    edge_t_kernel<<<(E * HID + 255) / 256, 256>>>(er, ew1, eb1, ew2, wih, whh, E);
    we_gemm_kernel<<<(E + 15) / 16, 128>>>(eb2, E);

    for (int step = 0; step < 3; step++) {
        msg_kernel<<<(E / 2 + 7) / 8, 256>>>(esrc, edst, E, N);
        gru_kernel<<<1184, 256>>>(bih, bhh, conv_b, (float*)d_out, N, step == 2);
    }
}

// round 14
// speedup vs baseline: 1.1240x; 1.1117x over previous
#include <cuda_runtime.h>
#include <cuda_fp16.h>
#include <math.h>

#define HID   32
#define BATCH 2
#define NMAX  55296
#define EMAX  221184
#define COLT  256

typedef unsigned long long ull;

__device__ __forceinline__ void fma2(ull& acc, ull a, ull b) {
    asm("fma.rn.f32x2 %0, %1, %2, %0;" : "+l"(acc) : "l"(a), "l"(b));
}
__device__ __forceinline__ ull pack2(float lo, float hi) {
    ull r; asm("mov.b64 %0, {%1, %2};" : "=l"(r) : "f"(lo), "f"(hi)); return r;
}
__device__ __forceinline__ float2 unpack2(ull v) {
    float2 r; asm("mov.b64 {%0, %1}, %2;" : "=f"(r.x), "=f"(r.y) : "l"(v)); return r;
}

// ---- scratch (device globals: allocation-free rule) ----
__device__ float  g_t[EMAX * HID];                         //  28 MB
// layout: [e][y][o][hl]  (y = h>>3, hl = h&7): half index = e*1024 + y*256 + o*8 + hl
__device__ __half g_We[(size_t)EMAX * HID * HID];          // 453 MB fp16
__device__ float  g_state[BATCH * NMAX * HID];             //  14 MB
__device__ float  g_agg[BATCH * NMAX * HID];               //  14 MB
__device__ float2 g_gruW[3 * HID * HID];                   // 24 KB packed (wih,whh) transposed

// ---------------- h0 = ReLU(x@pw1+pb1)@pw2+pb2  (+ agg init fused) ----------------
__global__ void node_mlp_kernel(const float* __restrict__ x,
                                const float* __restrict__ pw1, const float* __restrict__ pb1,
                                const float* __restrict__ pw2, const float* __restrict__ pb2,
                                const float* __restrict__ conv_b, int rows) {
    __shared__ float w1[HID * HID], w2[HID * HID], b1[HID], b2[HID], cb[HID];
    int tid = threadIdx.x;
    for (int i = tid; i < HID * HID; i += blockDim.x) { w1[i] = pw1[i]; w2[i] = pw2[i]; }
    if (tid < HID) { b1[tid] = pb1[tid]; b2[tid] = pb2[tid]; cb[tid] = conv_b[tid]; }
    __syncthreads();
    int warp = tid >> 5, lane = tid & 31;
    int row = blockIdx.x * (blockDim.x >> 5) + warp;
    if (row >= rows) return;
    float xv = x[row * HID + lane];
    float h1 = b1[lane];
#pragma unroll
    for (int k = 0; k < HID; k++)
        h1 = fmaf(__shfl_sync(0xffffffffu, xv, k), w1[k * HID + lane], h1);
    h1 = fmaxf(h1, 0.f);
    float h2 = b2[lane];
#pragma unroll
    for (int k = 0; k < HID; k++)
        h2 = fmaf(__shfl_sync(0xffffffffu, h1, k), w2[k * HID + lane], h2);
    g_state[row * HID + lane] = h2;
    g_agg[row * HID + lane] = cb[lane];     // fused init_agg
}

// ---------------- t = ReLU(er@ew1+eb1)  [E,32]  (+ GRU weight pack in block 0) ----------------
__global__ void edge_t_kernel(const float* __restrict__ er,
                              const float* __restrict__ ew1,
                              const float* __restrict__ eb1,
                              const float* __restrict__ wih,
                              const float* __restrict__ whh, int E) {
    int idx = blockIdx.x * blockDim.x + threadIdx.x;
    if (blockIdx.x == 0) {
        for (int i = threadIdx.x; i < 3 * HID * HID; i += blockDim.x) {
            int g = i >> 10, r = i & 1023, k = r >> 5, l = r & 31;
            int j = g * HID + l;
            g_gruW[i] = make_float2(wih[j * HID + k], whh[j * HID + k]);
        }
    }
    if (idx >= E * HID) return;
    int e = idx >> 5, l = idx & 31;
    float acc = eb1[l];
#pragma unroll
    for (int m = 0; m < 4; m++)
        acc = fmaf(er[e * 4 + m], ew1[m * HID + l], acc);
    g_t[idx] = fmaxf(acc, 0.f);
}

// ---------------- We = t @ ew2 + eb2, fp16, blocked layout [e][y][o][8h] ----------------
// f32x2 packed FMA, 8 edges/warp, 256-col tile (R6 version; measured 300us)
__global__ void __launch_bounds__(256, 2)
we_gemm_kernel(const float* __restrict__ ew2, const float* __restrict__ eb2, int E) {
    __shared__ float2 ws2[HID][4][32];   // 32 KB
    __shared__ float bs[COLT];
    int col0 = blockIdx.y * COLT;
    int tid = threadIdx.x;
    for (int i = tid; i < HID * 128; i += blockDim.x) {
        int k = i >> 7, r = i & 127, q = r >> 5, l = r & 31;
        ws2[k][q][l] = make_float2(ew2[k * (HID * HID) + col0 + q * 64 + l],
                                   ew2[k * (HID * HID) + col0 + q * 64 + 32 + l]);
    }
    for (int i = tid; i < COLT; i += blockDim.x) bs[i] = eb2[col0 + i];
    __syncthreads();

    int warp = tid >> 5, lane = tid & 31;
    int nwarps = blockDim.x >> 5;
    int groups = (E + 7) >> 3;
    float bias[8];
#pragma unroll
    for (int m = 0; m < 8; m++) bias[m] = bs[m * 32 + lane];

    for (int g = blockIdx.x * nwarps + warp; g < groups; g += gridDim.x * nwarps) {
        int e0 = g * 8;
        float t[8];
#pragma unroll
        for (int j = 0; j < 8; j++)
            t[j] = (e0 + j < E) ? g_t[(e0 + j) * HID + lane] : 0.f;

        ull acc[8][4];
#pragma unroll
        for (int j = 0; j < 8; j++)
#pragma unroll
            for (int q = 0; q < 4; q++) acc[j][q] = 0ull;

#pragma unroll
        for (int k = 0; k < HID; k++) {
            ull w0 = *(const ull*)&ws2[k][0][lane];
            ull w1 = *(const ull*)&ws2[k][1][lane];
            ull w2 = *(const ull*)&ws2[k][2][lane];
            ull w3 = *(const ull*)&ws2[k][3][lane];
#pragma unroll
            for (int j = 0; j < 8; j++) {
                float u = __shfl_sync(0xffffffffu, t[j], k);
                ull p = pack2(u, u);
                fma2(acc[j][0], p, w0);
                fma2(acc[j][1], p, w1);
                fma2(acc[j][2], p, w2);
                fma2(acc[j][3], p, w3);
            }
        }
#pragma unroll
        for (int j = 0; j < 8; j++) {
            int e = e0 + j;
            if (e < E) {
                float2 v0 = unpack2(acc[j][0]);
                float2 v1 = unpack2(acc[j][1]);
                float2 v2 = unpack2(acc[j][2]);
                float2 v3 = unpack2(acc[j][3]);
                __half2 p0 = __floats2half2_rn(v0.x + bias[0], v0.y + bias[1]);
                __half2 p1 = __floats2half2_rn(v1.x + bias[2], v1.y + bias[3]);
                __half2 p2 = __floats2half2_rn(v2.x + bias[4], v2.y + bias[5]);
                __half2 p3 = __floats2half2_rn(v3.x + bias[6], v3.y + bias[7]);
                uint4 val;
                val.x = *(unsigned*)&p0;
                val.y = *(unsigned*)&p1;
                val.z = *(unsigned*)&p2;
                val.w = *(unsigned*)&p3;
                *(uint4*)(g_We + (size_t)e * (HID * HID) + blockIdx.y * 256 + lane * 8) = val;
            }
        }
    }
}

// ---------------- msg + scatter: warp per 2 edges (MLP x2), fp16 We, v4 red ----------------
__global__ void msg_kernel(const int* __restrict__ src, const int* __restrict__ dst,
                           int E, int N) {
    int pair = (blockIdx.x * blockDim.x + threadIdx.x) >> 5;
    int lane = threadIdx.x & 31;
    int e0 = pair * 2;
    if (e0 >= E) return;
    int e1 = e0 + 1;
    bool has1 = (e1 < E);
    int sA = src[e0], dA = dst[e0];
    int sB = has1 ? src[e1] : sA;
    int dB = has1 ? dst[e1] : dA;

    float sa0 = g_state[sA * HID + lane];
    float sb0 = g_state[N * HID + sA * HID + lane];
    float sa1 = g_state[sB * HID + lane];
    float sb1 = g_state[N * HID + sB * HID + lane];

    const __half* WA = g_We + (size_t)e0 * (HID * HID) + lane * 8;
    const __half* WB = g_We + (size_t)e1 * (HID * HID) + lane * 8;
    uint4 wvA[4], wvB[4];
#pragma unroll
    for (int q = 0; q < 4; q++) {
        wvA[q] = *(const uint4*)(WA + q * 256);
        wvB[q] = has1 ? *(const uint4*)(WB + q * 256) : make_uint4(0, 0, 0, 0);
    }

    float mA0 = 0.f, mA1 = 0.f, mB0 = 0.f, mB1 = 0.f;
#pragma unroll
    for (int q = 0; q < 4; q++) {
        const __half2* hpA = (const __half2*)&wvA[q];
        const __half2* hpB = (const __half2*)&wvB[q];
#pragma unroll
        for (int j = 0; j < 4; j++) {
            float2 wA = __half22float2(hpA[j]);
            float2 wB = __half22float2(hpB[j]);
            int h = q * 8 + j * 2;
            float aA0 = __shfl_sync(0xffffffffu, sa0, h);
            float bA0 = __shfl_sync(0xffffffffu, sb0, h);
            float aA1 = __shfl_sync(0xffffffffu, sa0, h + 1);
            float bA1 = __shfl_sync(0xffffffffu, sb0, h + 1);
            float aB0 = __shfl_sync(0xffffffffu, sa1, h);
            float bB0 = __shfl_sync(0xffffffffu, sb1, h);
            float aB1 = __shfl_sync(0xffffffffu, sa1, h + 1);
            float bB1 = __shfl_sync(0xffffffffu, sb1, h + 1);
            mA0 = fmaf(aA0, wA.x, mA0); mA1 = fmaf(bA0, wA.x, mA1);
            mA0 = fmaf(aA1, wA.y, mA0); mA1 = fmaf(bA1, wA.y, mA1);
            mB0 = fmaf(aB0, wB.x, mB0); mB1 = fmaf(bB0, wB.x, mB1);
            mB0 = fmaf(aB1, wB.y, mB0); mB1 = fmaf(bB1, wB.y, mB1);
        }
    }
    int q4 = (lane & 7) * 4;
    {
        float t0 = __shfl_sync(0xffffffffu, mA0, q4 + 0);
        float t1 = __shfl_sync(0xffffffffu, mA0, q4 + 1);
        float t2 = __shfl_sync(0xffffffffu, mA0, q4 + 2);
        float t3 = __shfl_sync(0xffffffffu, mA0, q4 + 3);
        float u0 = __shfl_sync(0xffffffffu, mA1, q4 + 0);
        float u1 = __shfl_sync(0xffffffffu, mA1, q4 + 1);
        float u2 = __shfl_sync(0xffffffffu, mA1, q4 + 2);
        float u3 = __shfl_sync(0xffffffffu, mA1, q4 + 3);
        if (lane < 16) {
            float v0, v1, v2, v3; float* p;
            if (lane < 8) { v0 = t0; v1 = t1; v2 = t2; v3 = t3; p = &g_agg[dA * HID + q4]; }
            else          { v0 = u0; v1 = u1; v2 = u2; v3 = u3; p = &g_agg[N * HID + dA * HID + q4]; }
            asm volatile("red.global.add.v4.f32 [%0], {%1, %2, %3, %4};"
                         :: "l"(p), "f"(v0), "f"(v1), "f"(v2), "f"(v3) : "memory");
        }
    }
    if (has1) {
        float t0 = __shfl_sync(0xffffffffu, mB0, q4 + 0);
        float t1 = __shfl_sync(0xffffffffu, mB0, q4 + 1);
        float t2 = __shfl_sync(0xffffffffu, mB0, q4 + 2);
        float t3 = __shfl_sync(0xffffffffu, mB0, q4 + 3);
        float u0 = __shfl_sync(0xffffffffu, mB1, q4 + 0);
        float u1 = __shfl_sync(0xffffffffu, mB1, q4 + 1);
        float u2 = __shfl_sync(0xffffffffu, mB1, q4 + 2);
        float u3 = __shfl_sync(0xffffffffu, mB1, q4 + 3);
        if (lane < 16) {
            float v0, v1, v2, v3; float* p;
            if (lane < 8) { v0 = t0; v1 = t1; v2 = t2; v3 = t3; p = &g_agg[dB * HID + q4]; }
            else          { v0 = u0; v1 = u1; v2 = u2; v3 = u3; p = &g_agg[N * HID + dB * HID + q4]; }
            asm volatile("red.global.add.v4.f32 [%0], {%1, %2, %3, %4};"
                         :: "l"(p), "f"(v0), "f"(v1), "f"(v2), "f"(v3) : "memory");
        }
    }
}

// ---------------- GRU: persistent, warp = 4 nodes, both batches, f32x2 packed ----------------
// 3 LDS.64 weight loads per k serve 4 nodes x 2 batches: smem/node 24.6KB -> 6.1KB
__global__ void __launch_bounds__(256)
gru_kernel(const float* __restrict__ bih, const float* __restrict__ bhh,
           const float* __restrict__ conv_b,
           float* __restrict__ dout, int N, int final_step) {
    __shared__ float2 W2[3 * HID * HID];   // 24 KB, layout [(g*32+k)*32+l]
    __shared__ float bi[3 * HID], bh[3 * HID], cb[HID];
    int tid = threadIdx.x;
    for (int i = tid; i < 3 * HID * HID; i += blockDim.x) W2[i] = g_gruW[i];
    for (int i = tid; i < 3 * HID; i += blockDim.x) { bi[i] = bih[i]; bh[i] = bhh[i]; }
    if (tid < HID) cb[tid] = conv_b[tid];
    __syncthreads();

    int warp = tid >> 5, lane = tid & 31;
    int nwarps = blockDim.x >> 5;
    int tasks = (N + 3) >> 2;
    ull br = pack2(bi[lane], bh[lane]);
    ull bz = pack2(bi[32 + lane], bh[32 + lane]);
    ull bn = pack2(bi[64 + lane], bh[64 + lane]);

    for (int task = blockIdx.x * nwarps + warp; task < tasks; task += gridDim.x * nwarps) {
        int n0 = task * 4;
        float a0[4], a1[4], h0[4], h1[4];
#pragma unroll
        for (int j = 0; j < 4; j++) {
            int n = n0 + j;
            int ok = (n < N);
            int i0 = (ok ? n : 0) * HID + lane;
            int i1 = N * HID + i0;
            a0[j] = ok ? fmaxf(g_agg[i0], 0.f) : 0.f;
            a1[j] = ok ? fmaxf(g_agg[i1], 0.f) : 0.f;
            h0[j] = ok ? g_state[i0] : 0.f;
            h1[j] = ok ? g_state[i1] : 0.f;
        }

        ull r0[4], z0[4], nv0[4], r1[4], z1[4], nv1[4];
#pragma unroll
        for (int j = 0; j < 4; j++) {
            r0[j] = br; z0[j] = bz; nv0[j] = bn;
            r1[j] = br; z1[j] = bz; nv1[j] = bn;
        }
#pragma unroll
        for (int k = 0; k < HID; k++) {
            ull wr = *(const ull*)&W2[(0 * HID + k) * HID + lane];
            ull wz = *(const ull*)&W2[(1 * HID + k) * HID + lane];
            ull wn = *(const ull*)&W2[(2 * HID + k) * HID + lane];
#pragma unroll
            for (int j = 0; j < 4; j++) {
                float ak0 = __shfl_sync(0xffffffffu, a0[j], k);
                float hk0 = __shfl_sync(0xffffffffu, h0[j], k);
                float ak1 = __shfl_sync(0xffffffffu, a1[j], k);
                float hk1 = __shfl_sync(0xffffffffu, h1[j], k);
                ull xh0 = pack2(ak0, hk0);
                ull xh1 = pack2(ak1, hk1);
                fma2(r0[j], xh0, wr); fma2(r1[j], xh1, wr);
                fma2(z0[j], xh0, wz); fma2(z1[j], xh1, wz);
                fma2(nv0[j], xh0, wn); fma2(nv1[j], xh1, wn);
            }
        }
#pragma unroll
        for (int j = 0; j < 4; j++) {
            int n = n0 + j;
            if (n >= N) break;
            int i0 = n * HID + lane;
            int i1 = N * HID + i0;
            float2 vr0 = unpack2(r0[j]), vz0 = unpack2(z0[j]), vn0 = unpack2(nv0[j]);
            float2 vr1 = unpack2(r1[j]), vz1 = unpack2(z1[j]), vn1 = unpack2(nv1[j]);

            float rr0 = 1.f / (1.f + expf(-(vr0.x + vr0.y)));
            float zz0 = 1.f / (1.f + expf(-(vz0.x + vz0.y)));
            float nn0 = tanhf(vn0.x + rr0 * vn0.y);
            float out0 = (1.f - zz0) * nn0 + zz0 * h0[j];

            float rr1 = 1.f / (1.f + expf(-(vr1.x + vr1.y)));
            float zz1 = 1.f / (1.f + expf(-(vz1.x + vz1.y)));
            float nn1 = tanhf(vn1.x + rr1 * vn1.y);
            float out1 = (1.f - zz1) * nn1 + zz1 * h1[j];

            g_state[i0] = out0;
            g_state[i1] = out1;
            if (final_step) {
                dout[i0] = out0;
                dout[i1] = out1;
            } else {
                g_agg[i0] = cb[lane];
                g_agg[i1] = cb[lane];
            }
        }
    }
}

extern "C" void kernel_launch(void* const* d_in, const int* in_sizes, int n_in,
                              void* d_out, int out_size) {
    const float* x      = (const float*)d_in[0];
    const float* er     = (const float*)d_in[1];
    const float* pw1    = (const float*)d_in[2];
    const float* pb1    = (const float*)d_in[3];
    const float* pw2    = (const float*)d_in[4];
    const float* pb2    = (const float*)d_in[5];
    const float* ew1    = (const float*)d_in[6];
    const float* eb1    = (const float*)d_in[7];
    const float* ew2    = (const float*)d_in[8];
    const float* eb2    = (const float*)d_in[9];
    const float* conv_b = (const float*)d_in[10];
    const float* wih    = (const float*)d_in[11];
    const float* whh    = (const float*)d_in[12];
    const float* bih    = (const float*)d_in[13];
    const float* bhh    = (const float*)d_in[14];
    const int*   esrc   = (const int*)d_in[15];
    const int*   edst   = (const int*)d_in[16];

    int E = in_sizes[15];
    int N = in_sizes[0] / (BATCH * HID);
    int rows = BATCH * N;

    node_mlp_kernel<<<(rows + 7) / 8, 256>>>(x, pw1, pb1, pw2, pb2, conv_b, rows);
    edge_t_kernel<<<(E * HID + 255) / 256, 256>>>(er, ew1, eb1, wih, whh, E);
    {
        dim3 grid(1728, 4);
        we_gemm_kernel<<<grid, 256>>>(ew2, eb2, E);
    }

    for (int step = 0; step < 3; step++) {
        msg_kernel<<<(E / 2 + 7) / 8, 256>>>(esrc, edst, E, N);
        gru_kernel<<<592, 256>>>(bih, bhh, conv_b, (float*)d_out, N, step == 2);
    }
}